// round 5
// baseline (speedup 1.0000x reference)
#include <cuda_runtime.h>
#include <cuda_bf16.h>
#include <math.h>
#include <stdint.h>

#define BB 32
#define NN 385
#define DIM 512
#define HH 8
#define HD 64
#define TDIM 1536
#define MLP 2048
#define KA 45
#define KM 135
#define KS 90
#define RN 271
#define M1 (BB*NN)
#define M2 (BB*RN)

#define X_SZ   ((long long)BB*RN*DIM)
#define OFF_IA (X_SZ)
#define OFF_IM (OFF_IA + (long long)BB*KA)
#define OFF_IS (OFF_IM + (long long)BB*KM)
#define OFF_MASK (OFF_IS + (long long)BB*KS)
#define MASK_SZ ((long long)BB*RN*RN)

__device__ float g_xn  [M1*DIM];
__device__ float g_qkv [(size_t)M1*TDIM];
__device__ float g_xatt[M1*DIM];
__device__ float g_xres[M1*DIM];
__device__ float g_clsP[BB*HH*384];
__device__ float g_cls [BB*384];
__device__ int   g_idx [BB*(KA+KM+KS)];
__device__ float g_xg  [M2*DIM];
__device__ float g_xn2 [M2*DIM];
__device__ float g_h   [(size_t)M2*MLP];

__device__ __forceinline__ float tf32_rn(float x) {
    uint32_t u; asm("cvt.rna.tf32.f32 %0, %1;" : "=r"(u) : "f"(x));
    return __uint_as_float(u);
}
__device__ __forceinline__ void mma8(float* c, const uint32_t* a, const uint32_t* b) {
    asm volatile("mma.sync.aligned.m16n8k8.row.col.f32.tf32.tf32.f32 "
        "{%0,%1,%2,%3}, {%4,%5,%6,%7}, {%8,%9}, {%0,%1,%2,%3};\n"
        : "+f"(c[0]), "+f"(c[1]), "+f"(c[2]), "+f"(c[3])
        : "r"(a[0]), "r"(a[1]), "r"(a[2]), "r"(a[3]), "r"(b[0]), "r"(b[1]));
}
__device__ __forceinline__ unsigned pack_bf(float x, float y) {
    __nv_bfloat162 p = __floats2bfloat162_rn(x, y);
    return *reinterpret_cast<unsigned*>(&p);
}
__device__ __forceinline__ float2 unpack_bf(unsigned u) {
    __nv_bfloat162 p = *reinterpret_cast<__nv_bfloat162*>(&u);
    return __bfloat1622float2(p);
}

// ---------------- LayerNorm ----------------
__global__ void ln_kernel(const float* __restrict__ in, const float* __restrict__ g,
                          const float* __restrict__ bta, float* __restrict__ out) {
    int r = blockIdx.x, t = threadIdx.x;
    const float* xr = in + (size_t)r * DIM;
    float a = xr[t], c = xr[t + 256];
    __shared__ float rs[256], rq[256];
    rs[t] = a + c; rq[t] = a*a + c*c;
    __syncthreads();
    for (int st = 128; st > 0; st >>= 1) {
        if (t < st) { rs[t] += rs[t+st]; rq[t] += rq[t+st]; }
        __syncthreads();
    }
    float mu  = rs[0] * (1.0f/512.0f);
    float var = rq[0] * (1.0f/512.0f) - mu*mu;
    float inv = rsqrtf(var + 1e-5f);
    out[(size_t)r*DIM + t]       = (a - mu) * inv * g[t]     + bta[t];
    out[(size_t)r*DIM + t + 256] = (c - mu) * inv * g[t+256] + bta[t+256];
}

// ---------------- fp32 SGEMM (proven numerics) with ldc ----------------
__global__ void gemm_f32(const float* __restrict__ A, const float* __restrict__ Bw,
                         float* __restrict__ C, int M, int Nc, int K, int ldc) {
    const int BK = 8;
    __shared__ float As[BK][128];
    __shared__ float Bs[BK][128];
    int bm = blockIdx.y * 128, bn = blockIdx.x * 128;
    int tid = threadIdx.x;
    int tx = tid & 15, ty = tid >> 4;
    int lr = tid >> 1, lc = (tid & 1) * 4;

    float acc[8][8];
#pragma unroll
    for (int i = 0; i < 8; i++)
#pragma unroll
        for (int j = 0; j < 8; j++) acc[i][j] = 0.f;

    for (int k0 = 0; k0 < K; k0 += BK) {
        int gr = bm + lr;
        float4 a4 = make_float4(0.f,0.f,0.f,0.f);
        if (gr < M) a4 = *reinterpret_cast<const float4*>(&A[(size_t)gr*K + k0 + lc]);
        As[lc+0][lr] = a4.x; As[lc+1][lr] = a4.y; As[lc+2][lr] = a4.z; As[lc+3][lr] = a4.w;
        int gn = bn + lr;
        float4 b4 = *reinterpret_cast<const float4*>(&Bw[(size_t)gn*K + k0 + lc]);
        Bs[lc+0][lr] = b4.x; Bs[lc+1][lr] = b4.y; Bs[lc+2][lr] = b4.z; Bs[lc+3][lr] = b4.w;
        __syncthreads();
#pragma unroll
        for (int k = 0; k < BK; k++) {
            float4 a0 = *reinterpret_cast<const float4*>(&As[k][ty*8]);
            float4 a1 = *reinterpret_cast<const float4*>(&As[k][ty*8+4]);
            float4 b0 = *reinterpret_cast<const float4*>(&Bs[k][tx*8]);
            float4 b1 = *reinterpret_cast<const float4*>(&Bs[k][tx*8+4]);
            float av[8] = {a0.x,a0.y,a0.z,a0.w,a1.x,a1.y,a1.z,a1.w};
            float bv[8] = {b0.x,b0.y,b0.z,b0.w,b1.x,b1.y,b1.z,b1.w};
#pragma unroll
            for (int i = 0; i < 8; i++)
#pragma unroll
                for (int j = 0; j < 8; j++) acc[i][j] += av[i]*bv[j];
        }
        __syncthreads();
    }
#pragma unroll
    for (int i = 0; i < 8; i++) {
        int row = bm + ty*8 + i;
        if (row >= M) continue;
#pragma unroll
        for (int j = 0; j < 8; j++)
            C[(size_t)row*ldc + bn + tx*8 + j] = acc[i][j];
    }
}

// ---------------- exact q0 for cls tokens (bit-matches gemm_f32 chain) ----------------
__global__ void q0_exact(const float* __restrict__ Wq) {
    int b = blockIdx.x, d = threadIdx.x;   // 512 threads
    __shared__ float xr[512];
    xr[d] = g_xn[((size_t)b*NN)*DIM + d];
    __syncthreads();
    const float* wr = Wq + (size_t)d*DIM;
    float s = 0.f;
#pragma unroll 4
    for (int c = 0; c < 512; c += 4) {
        float4 w4 = *reinterpret_cast<const float4*>(&wr[c]);
        float4 x4 = *reinterpret_cast<const float4*>(&xr[c]);
        s = fmaf(w4.x, x4.x, s);
        s = fmaf(w4.y, x4.y, s);
        s = fmaf(w4.z, x4.z, s);
        s = fmaf(w4.w, x4.w, s);
    }
    g_qkv[(size_t)b*NN*TDIM + d] = s;
}

// ---------------- TF32 MMA GEMM with ldc ----------------
#define GTS (128*20)
template<int EPI>
__device__ __forceinline__ float epi_f(float v, const float* bias, const float* res,
                                       size_t row, int col, int ldc) {
    if (EPI == 1) v += bias[col] + res[row*(size_t)ldc + col];
    if (EPI == 2) { v += bias[col]; v = 0.5f*v*(1.0f + erff(v*0.70710678118654752f)); }
    return v;
}
__device__ __forceinline__ void cvt_store4(float* hi, int idx, float4 v) {
    *(float4*)&hi[idx] = make_float4(tf32_rn(v.x), tf32_rn(v.y), tf32_rn(v.z), tf32_rn(v.w));
}

template<int EPI>
__global__ void __launch_bounds__(256) gemm_mma(
    const float* __restrict__ A, const float* __restrict__ Bw,
    const float* __restrict__ bias, const float* __restrict__ res,
    float* __restrict__ C, int M, int Nc, int K, int ldc)
{
    extern __shared__ float sm[];
    float* Ah = sm;
    float* Bh = sm + 2*GTS;

    int tid = threadIdx.x;
    int bm = blockIdx.y*128, bn = blockIdx.x*128;
    int lane = tid & 31, g = lane >> 2, tg = lane & 3;
    int warp = tid >> 5;
    int wm = (warp & 1) * 64, wn = (warp >> 1) * 32;

    int r0 = tid >> 2;
    int c0 = (tid & 3) * 4;
    bool v0 = (bm + r0) < M;
    bool v1 = (bm + r0 + 64) < M;
    const float* Ag0 = A  + (size_t)(bm + r0)      * K + c0;
    const float* Ag1 = A  + (size_t)(bm + r0 + 64) * K + c0;
    const float* Bg0 = Bw + (size_t)(bn + r0)      * K + c0;
    const float* Bg1 = Bw + (size_t)(bn + r0 + 64) * K + c0;

    float acc[4][4][4];
#pragma unroll
    for (int i = 0; i < 4; i++)
#pragma unroll
        for (int j = 0; j < 4; j++)
#pragma unroll
            for (int e = 0; e < 4; e++) acc[i][j][e] = 0.f;

    const float4 z4 = make_float4(0.f,0.f,0.f,0.f);
    cvt_store4(Ah, r0*20 + c0,      v0 ? *(const float4*)Ag0 : z4);
    cvt_store4(Ah, (r0+64)*20 + c0, v1 ? *(const float4*)Ag1 : z4);
    cvt_store4(Bh, r0*20 + c0,      *(const float4*)Bg0);
    cvt_store4(Bh, (r0+64)*20 + c0, *(const float4*)Bg1);
    __syncthreads();

    int KT = K >> 4;
    for (int kt = 0; kt < KT; kt++) {
        int buf = kt & 1;
        bool more = (kt + 1) < KT;
        float4 na0, na1, nb0, nb1;
        if (more) {
            int ko = (kt + 1) * 16;
            na0 = v0 ? *(const float4*)(Ag0 + ko) : z4;
            na1 = v1 ? *(const float4*)(Ag1 + ko) : z4;
            nb0 = *(const float4*)(Bg0 + ko);
            nb1 = *(const float4*)(Bg1 + ko);
        }
        const float* As = Ah + buf*GTS;
        const float* Bs = Bh + buf*GTS;
#pragma unroll
        for (int ks = 0; ks < 2; ks++) {
            int kb = ks*8 + tg;
            uint32_t af[4][4], bf[4][2];
#pragma unroll
            for (int i = 0; i < 4; i++) {
                int r = wm + i*16 + g;
                af[i][0] = __float_as_uint(As[r*20 + kb]);
                af[i][1] = __float_as_uint(As[(r+8)*20 + kb]);
                af[i][2] = __float_as_uint(As[r*20 + kb + 4]);
                af[i][3] = __float_as_uint(As[(r+8)*20 + kb + 4]);
            }
#pragma unroll
            for (int j = 0; j < 4; j++) {
                int n = wn + j*8 + g;
                bf[j][0] = __float_as_uint(Bs[n*20 + kb]);
                bf[j][1] = __float_as_uint(Bs[n*20 + kb + 4]);
            }
#pragma unroll
            for (int i = 0; i < 4; i++)
#pragma unroll
                for (int j = 0; j < 4; j++) mma8(acc[i][j], af[i], bf[j]);
        }
        if (more) {
            int nb2 = (buf ^ 1) * GTS;
            cvt_store4(Ah, nb2 + r0*20 + c0,      na0);
            cvt_store4(Ah, nb2 + (r0+64)*20 + c0, na1);
            cvt_store4(Bh, nb2 + r0*20 + c0,      nb0);
            cvt_store4(Bh, nb2 + (r0+64)*20 + c0, nb1);
            __syncthreads();
        }
    }

#pragma unroll
    for (int i = 0; i < 4; i++) {
        int rr0 = bm + wm + i*16 + g;
        int rr1 = rr0 + 8;
#pragma unroll
        for (int j = 0; j < 4; j++) {
            int c = bn + wn + j*8 + tg*2;
            if (rr0 < M) {
                C[(size_t)rr0*ldc + c  ] = epi_f<EPI>(acc[i][j][0], bias, res, rr0, c,   ldc);
                C[(size_t)rr0*ldc + c+1] = epi_f<EPI>(acc[i][j][1], bias, res, rr0, c+1, ldc);
            }
            if (rr1 < M) {
                C[(size_t)rr1*ldc + c  ] = epi_f<EPI>(acc[i][j][2], bias, res, rr1, c,   ldc);
                C[(size_t)rr1*ldc + c+1] = epi_f<EPI>(acc[i][j][3], bias, res, rr1, c+1, ldc);
            }
        }
    }
}

// ---------------- fused attention: bf16 K/V/Q in smem, exact cls row ----------------
// smem layout (uint words): Kb[385*36] | Vb[385*33] | pad | q4b[128] | q0f[64] | wred[64] | sc/part[2048]
#define KP 36
#define VP 33
#define OFF_Q4  26568
#define OFF_Q0  26696
#define OFF_WRD 26760
#define OFF_SC  26824
#define ATTN_WORDS (26824 + 2048)

__global__ void __launch_bounds__(256,2) attn_kernel(const float* __restrict__ mask) {
    extern __shared__ unsigned smu[];
    unsigned* Kb  = smu;
    unsigned* Vb  = smu + 385*KP;
    unsigned* q4b = smu + OFF_Q4;
    float* q0f  = (float*)(smu + OFF_Q0);
    float* wred = (float*)(smu + OFF_WRD);   // [0:32) max, [32:64) sum
    float* sc   = (float*)(smu + OFF_SC);    // 4 planes pitch 385; reused as part[2048]
    float* part = sc;

    int bh = blockIdx.x, b = bh >> 3, h = bh & 7;
    int t = threadIdx.x, lane = t & 31, w = t >> 5;
    const float* qkvb = g_qkv + (size_t)b * NN * TDIM;

    // load K/V as bf16x2
    for (int i = t; i < NN*16; i += 256) {
        int m = i >> 4, d8 = i & 15;
        float4 kv = *(const float4*)&qkvb[(size_t)m*TDIM + DIM   + h*HD + d8*4];
        Kb[m*KP + d8*2]     = pack_bf(kv.x, kv.y);
        Kb[m*KP + d8*2 + 1] = pack_bf(kv.z, kv.w);
        float4 vv = *(const float4*)&qkvb[(size_t)m*TDIM + 2*DIM + h*HD + d8*4];
        Vb[m*VP + d8*2]     = pack_bf(vv.x, vv.y);
        Vb[m*VP + d8*2 + 1] = pack_bf(vv.z, vv.w);
    }
    __syncthreads();

    const float addc = 1e-6f / 385.0f;
    const float* mb = mask + (size_t)b * NN * NN;

    for (int n0 = 0; n0 < NN; n0 += 4) {
        // load 4 query rows (bf16); iter 0 also loads exact fp32 q0
        if (t < 128) {
            int q = t >> 5, p = t & 31;
            int nq = n0 + q; if (nq > NN-1) nq = NN-1;
            float2 qv = *(const float2*)&qkvb[(size_t)nq*TDIM + h*HD + p*2];
            q4b[q*32 + p] = pack_bf(qv.x, qv.y);
        } else if (n0 == 0 && t >= 192) {
            q0f[t - 192] = qkvb[h*HD + (t - 192)];
        }
        __syncthreads();                                   // S1

        // ---- scores (bf16) ----
        float lm0=-1e30f, lm1=-1e30f, lm2=-1e30f, lm3=-1e30f;
        for (int m = t; m < NN; m += 256) {
            float s0=0.f, s1=0.f, s2=0.f, s3=0.f;
            const unsigned* kr = &Kb[m*KP];
#pragma unroll
            for (int dg = 0; dg < 8; dg++) {
                uint4 kw = *(const uint4*)&kr[dg*4];
                float2 k0 = unpack_bf(kw.x), k1 = unpack_bf(kw.y);
                float2 k2 = unpack_bf(kw.z), k3 = unpack_bf(kw.w);
                uint4 qw = *(const uint4*)&q4b[dg*4];
                {   float2 a=unpack_bf(qw.x), bq=unpack_bf(qw.y), c=unpack_bf(qw.z), dq=unpack_bf(qw.w);
                    s0 += k0.x*a.x + k0.y*a.y + k1.x*bq.x + k1.y*bq.y
                        + k2.x*c.x + k2.y*c.y + k3.x*dq.x + k3.y*dq.y; }
                qw = *(const uint4*)&q4b[32 + dg*4];
                {   float2 a=unpack_bf(qw.x), bq=unpack_bf(qw.y), c=unpack_bf(qw.z), dq=unpack_bf(qw.w);
                    s1 += k0.x*a.x + k0.y*a.y + k1.x*bq.x + k1.y*bq.y
                        + k2.x*c.x + k2.y*c.y + k3.x*dq.x + k3.y*dq.y; }
                qw = *(const uint4*)&q4b[64 + dg*4];
                {   float2 a=unpack_bf(qw.x), bq=unpack_bf(qw.y), c=unpack_bf(qw.z), dq=unpack_bf(qw.w);
                    s2 += k0.x*a.x + k0.y*a.y + k1.x*bq.x + k1.y*bq.y
                        + k2.x*c.x + k2.y*c.y + k3.x*dq.x + k3.y*dq.y; }
                qw = *(const uint4*)&q4b[96 + dg*4];
                {   float2 a=unpack_bf(qw.x), bq=unpack_bf(qw.y), c=unpack_bf(qw.z), dq=unpack_bf(qw.w);
                    s3 += k0.x*a.x + k0.y*a.y + k1.x*bq.x + k1.y*bq.y
                        + k2.x*c.x + k2.y*c.y + k3.x*dq.x + k3.y*dq.y; }
            }
            s0 *= 0.125f; s1 *= 0.125f; s2 *= 0.125f; s3 *= 0.125f;
            sc[m] = s0; sc[385+m] = s1; sc[770+m] = s2; sc[1155+m] = s3;
            lm0 = fmaxf(lm0, s0); lm1 = fmaxf(lm1, s1);
            lm2 = fmaxf(lm2, s2); lm3 = fmaxf(lm3, s3);
        }
        // ---- exact cls-row scores (fp32 from gmem, R4-identical expression) ----
        if (n0 == 0) {
            lm0 = -1e30f;
            const float* kg = qkvb + DIM + h*HD;
            for (int m = t; m < NN; m += 256) {
                float s0 = 0.f;
#pragma unroll
                for (int d4 = 0; d4 < 64; d4 += 4) {
                    float4 k  = *(const float4*)&kg[(size_t)m*TDIM + d4];
                    float4 qa = *(const float4*)&q0f[d4];
                    s0 += k.x*qa.x + k.y*qa.y + k.z*qa.z + k.w*qa.w;
                }
                s0 *= 0.125f;
                sc[m] = s0;
                lm0 = fmaxf(lm0, s0);
            }
        }
#pragma unroll
        for (int off = 16; off; off >>= 1) {
            lm0 = fmaxf(lm0, __shfl_xor_sync(0xFFFFFFFFu, lm0, off));
            lm1 = fmaxf(lm1, __shfl_xor_sync(0xFFFFFFFFu, lm1, off));
            lm2 = fmaxf(lm2, __shfl_xor_sync(0xFFFFFFFFu, lm2, off));
            lm3 = fmaxf(lm3, __shfl_xor_sync(0xFFFFFFFFu, lm3, off));
        }
        if (lane == 0) { wred[w*4+0]=lm0; wred[w*4+1]=lm1; wred[w*4+2]=lm2; wred[w*4+3]=lm3; }
        __syncthreads();                                   // S2

        float bm0=wred[0], bm1=wred[1], bm2=wred[2], bm3=wred[3];
#pragma unroll
        for (int wi = 1; wi < 8; wi++) {
            bm0 = fmaxf(bm0, wred[wi*4+0]); bm1 = fmaxf(bm1, wred[wi*4+1]);
            bm2 = fmaxf(bm2, wred[wi*4+2]); bm3 = fmaxf(bm3, wred[wi*4+3]);
        }

        float ls0=0.f, ls1=0.f, ls2=0.f, ls3=0.f;
        int nq1 = (n0+1 < NN) ? n0+1 : NN-1;
        int nq2 = (n0+2 < NN) ? n0+2 : NN-1;
        int nq3 = (n0+3 < NN) ? n0+3 : NN-1;
        const float* mr0 = mb + (size_t)n0  * NN;
        const float* mr1 = mb + (size_t)nq1 * NN;
        const float* mr2 = mb + (size_t)nq2 * NN;
        const float* mr3 = mb + (size_t)nq3 * NN;
        for (int m = t; m < NN; m += 256) {
            float e0 = expf(sc[m]      - bm0) * mr0[m];
            float e1 = expf(sc[385+m]  - bm1) * mr1[m];
            float e2 = expf(sc[770+m]  - bm2) * mr2[m];
            float e3 = expf(sc[1155+m] - bm3) * mr3[m];
            sc[m] = e0; sc[385+m] = e1; sc[770+m] = e2; sc[1155+m] = e3;
            ls0 += e0; ls1 += e1; ls2 += e2; ls3 += e3;
        }
#pragma unroll
        for (int off = 16; off; off >>= 1) {
            ls0 += __shfl_xor_sync(0xFFFFFFFFu, ls0, off);
            ls1 += __shfl_xor_sync(0xFFFFFFFFu, ls1, off);
            ls2 += __shfl_xor_sync(0xFFFFFFFFu, ls2, off);
            ls3 += __shfl_xor_sync(0xFFFFFFFFu, ls3, off);
        }
        if (lane == 0) { wred[32+w*4+0]=ls0; wred[32+w*4+1]=ls1; wred[32+w*4+2]=ls2; wred[32+w*4+3]=ls3; }
        __syncthreads();                                   // S3

        float sm0=0.f, sm1=0.f, sm2=0.f, sm3=0.f;
#pragma unroll
        for (int wi = 0; wi < 8; wi++) {
            sm0 += wred[32+wi*4+0]; sm1 += wred[32+wi*4+1];
            sm2 += wred[32+wi*4+2]; sm3 += wred[32+wi*4+3];
        }
        float iv0 = 1.0f/(sm0+1e-6f), iv1 = 1.0f/(sm1+1e-6f);
        float iv2 = 1.0f/(sm2+1e-6f), iv3 = 1.0f/(sm3+1e-6f);

        if (n0 == 0) {
            for (int j = t; j < 384; j += 256)
                g_clsP[((size_t)b*HH + h)*384 + j] = (sc[1+j] + addc) * iv0 * 0.125f;
        }

        // ---- AV: warp owns m-stripe, lane owns dim-pair ----
        float ax0=0,ay0=0, ax1=0,ay1=0, ax2=0,ay2=0, ax3=0,ay3=0;
        for (int m = w; m < NN; m += 8) {
            float2 v = unpack_bf(Vb[m*VP + lane]);
            float p0 = (sc[m]      + addc) * iv0;
            float p1 = (sc[385+m]  + addc) * iv1;
            float p2 = (sc[770+m]  + addc) * iv2;
            float p3 = (sc[1155+m] + addc) * iv3;
            ax0 += p0*v.x; ay0 += p0*v.y;
            ax1 += p1*v.x; ay1 += p1*v.y;
            ax2 += p2*v.x; ay2 += p2*v.y;
            ax3 += p3*v.x; ay3 += p3*v.y;
        }
        __syncthreads();                                   // S4 (sc reads done)
        {
            int dd = lane*2;
            int base = (w*4)*64 + dd;
            part[base      ] = ax0; part[base + 1  ] = ay0;
            part[base + 64 ] = ax1; part[base + 65 ] = ay1;
            part[base + 128] = ax2; part[base + 129] = ay2;
            part[base + 192] = ax3; part[base + 193] = ay3;
        }
        __syncthreads();                                   // S5
        {
            int q = t >> 6, d = t & 63;
            int n = n0 + q;
            if (n < NN) {
                float s = 0.f;
#pragma unroll
                for (int sp = 0; sp < 8; sp++) s += part[(sp*4 + q)*64 + d];
                g_xatt[((size_t)(b*NN + n))*DIM + h*HD + d] = s;
            }
        }
        // next-iter S1 protects part reads vs next sc writes
    }
}

// ---------------- cls reduce ----------------
__global__ void cls_reduce_kernel() {
    int i = blockIdx.x*256 + threadIdx.x;
    if (i < BB*384) {
        int b = i / 384, j = i % 384;
        float s = 0.f;
#pragma unroll
        for (int h = 0; h < HH; h++) s += g_clsP[((size_t)b*HH + h)*384 + j];
        g_cls[i] = s;
    }
}

// ---------------- top-k (exact jax tie semantics) ----------------
__global__ void topk_kernel(float* __restrict__ out) {
    const int nsz_[3]  = {64, 192, 128};
    const int kk_[3]   = {KA, KM, KS};
    const int base_[3] = {0, 64, 256};
    const int ib_[3]   = {0, KA, KA+KM};
    const long long ob_[3] = {OFF_IA, OFF_IM, OFF_IS};
    const int os_[3]   = {KA, KM, KS};

    int b = blockIdx.x / 3, g = blockIdx.x % 3;
    int nsz = nsz_[g], kk = kk_[g];
    __shared__ float v[192];
    __shared__ float rv[256];
    __shared__ int   ri[256];
    int t = threadIdx.x;
    if (t < nsz) v[t] = g_cls[b*384 + base_[g] + t];
    __syncthreads();

    for (int i = 0; i < kk; i++) {
        rv[t] = (t < nsz) ? v[t] : -INFINITY;
        ri[t] = t;
        __syncthreads();
        for (int s = 128; s > 0; s >>= 1) {
            if (t < s) {
                float v2 = rv[t+s]; int i2 = ri[t+s];
                if (v2 > rv[t] || (v2 == rv[t] && i2 < ri[t])) { rv[t] = v2; ri[t] = i2; }
            }
            __syncthreads();
        }
        if (t == 0) {
            int wn = ri[0];
            g_idx[b*(KA+KM+KS) + ib_[g] + i] = wn;
            out[ob_[g] + (long long)b*os_[g] + i] = (float)wn;
            v[wn] = -INFINITY;
        }
        __syncthreads();
    }
}

// ---------------- gather ----------------
__global__ void gather_kernel() {
    int r = blockIdx.x;
    int b = r / RN, p = r % RN;
    int s;
    if (p == 0)            s = 0;
    else if (p < 1+KA)     s = 1   + g_idx[b*(KA+KM+KS) + (p-1)];
    else if (p < 1+KA+KM)  s = 65  + g_idx[b*(KA+KM+KS) + KA + (p-1-KA)];
    else                   s = 257 + g_idx[b*(KA+KM+KS) + KA+KM + (p-1-KA-KM)];
    const float4* src = reinterpret_cast<const float4*>(g_xres + ((size_t)(b*NN + s))*DIM);
    float4* dst = reinterpret_cast<float4*>(g_xg + (size_t)r*DIM);
    dst[threadIdx.x] = src[threadIdx.x];
}

// ---------------- mask = ones (vectorized) ----------------
__global__ void mask_fill_kernel(float* __restrict__ out) {
    long long i = (long long)blockIdx.x*256 + threadIdx.x;
    if (i < MASK_SZ/4) {
        float4* o = reinterpret_cast<float4*>(out + OFF_MASK);
        o[i] = make_float4(1.f,1.f,1.f,1.f);
    }
}

// ---------------- launcher ----------------
extern "C" void kernel_launch(void* const* d_in, const int* in_sizes, int n_in,
                              void* d_out, int out_size) {
    const float* x     = (const float*)d_in[0];
    const float* amask = (const float*)d_in[1];
    const float* Wqkv  = (const float*)d_in[5];
    const float* Wproj = (const float*)d_in[6];
    const float* bproj = (const float*)d_in[7];
    const float* g1    = (const float*)d_in[8];
    const float* b1    = (const float*)d_in[9];
    const float* g2    = (const float*)d_in[10];
    const float* b2    = (const float*)d_in[11];
    const float* Wfc1  = (const float*)d_in[12];
    const float* bfc1  = (const float*)d_in[13];
    const float* Wfc2  = (const float*)d_in[14];
    const float* bfc2  = (const float*)d_in[15];
    float* out = (float*)d_out;

    float *p_xn, *p_qkv, *p_xatt, *p_xres, *p_xg, *p_xn2, *p_h;
    cudaGetSymbolAddress((void**)&p_xn,   g_xn);
    cudaGetSymbolAddress((void**)&p_qkv,  g_qkv);
    cudaGetSymbolAddress((void**)&p_xatt, g_xatt);
    cudaGetSymbolAddress((void**)&p_xres, g_xres);
    cudaGetSymbolAddress((void**)&p_xg,   g_xg);
    cudaGetSymbolAddress((void**)&p_xn2,  g_xn2);
    cudaGetSymbolAddress((void**)&p_h,    g_h);

    const int SMEM_S = 4*GTS*4;                 // 40960 B
    const int ATTN_SMEM = ATTN_WORDS * 4;       // 115,488 B
    static int init_done = 0;
    if (!init_done) {
        cudaFuncSetAttribute(gemm_mma<0>, cudaFuncAttributeMaxDynamicSharedMemorySize, SMEM_S);
        cudaFuncSetAttribute(gemm_mma<1>, cudaFuncAttributeMaxDynamicSharedMemorySize, SMEM_S);
        cudaFuncSetAttribute(gemm_mma<2>, cudaFuncAttributeMaxDynamicSharedMemorySize, SMEM_S);
        cudaFuncSetAttribute(attn_kernel, cudaFuncAttributeMaxDynamicSharedMemorySize, ATTN_SMEM);
        init_done = 1;
    }

    ln_kernel<<<M1, 256>>>(x, g1, b1, p_xn);
    // Q (tf32), V (tf32), K (fp32 exact), q0 (fp32 exact, overwrites Q cls rows)
    gemm_mma<0><<<dim3(4, (M1+127)/128), 256, SMEM_S>>>(p_xn, Wqkv,            nullptr, nullptr, p_qkv,        M1, 512, DIM, TDIM);
    gemm_mma<0><<<dim3(4, (M1+127)/128), 256, SMEM_S>>>(p_xn, Wqkv + 1024*512, nullptr, nullptr, p_qkv + 1024, M1, 512, DIM, TDIM);
    gemm_f32<<<dim3(4, (M1+127)/128), 256>>>(p_xn, Wqkv + 512*512, p_qkv + 512, M1, 512, DIM, TDIM);
    q0_exact<<<BB, 512>>>(Wqkv);
    attn_kernel<<<BB*HH, 256, ATTN_SMEM>>>(amask);
    gemm_mma<1><<<dim3(DIM/128, (M1+127)/128), 256, SMEM_S>>>(p_xatt, Wproj, bproj, x, p_xres, M1, DIM, DIM, DIM);
    cls_reduce_kernel<<<(BB*384 + 255)/256, 256>>>();
    topk_kernel<<<BB*3, 256>>>(out);
    gather_kernel<<<M2, 128>>>();
    mask_fill_kernel<<<(int)((MASK_SZ/4 + 255)/256), 256>>>(out);
    ln_kernel<<<M2, 256>>>(p_xg, g2, b2, p_xn2);
    gemm_mma<2><<<dim3(MLP/128, (M2+127)/128), 256, SMEM_S>>>(p_xn2, Wfc1, bfc1, nullptr, p_h, M2, MLP, DIM, MLP);
    gemm_mma<1><<<dim3(DIM/128, (M2+127)/128), 256, SMEM_S>>>(p_h, Wfc2, bfc2, p_xg, out, M2, DIM, MLP, DIM);
}

// round 6
// speedup vs baseline: 1.1026x; 1.1026x over previous
#include <cuda_runtime.h>
#include <math.h>
#include <stdint.h>

#define BB 32
#define NN 385
#define DIM 512
#define HH 8
#define HD 64
#define TDIM 1536
#define MLP 2048
#define KA 45
#define KM 135
#define KS 90
#define RN 271
#define M1 (BB*NN)
#define M2 (BB*RN)

#define X_SZ   ((long long)BB*RN*DIM)
#define OFF_IA (X_SZ)
#define OFF_IM (OFF_IA + (long long)BB*KA)
#define OFF_IS (OFF_IM + (long long)BB*KM)
#define OFF_MASK (OFF_IS + (long long)BB*KS)
#define MASK_SZ ((long long)BB*RN*RN)

__device__ float g_xn  [M1*DIM];
__device__ float g_qkv [(size_t)M1*TDIM];
__device__ float g_xatt[M1*DIM];
__device__ float g_xres[M1*DIM];
__device__ float g_clsP[BB*HH*384];
__device__ float g_cls [BB*384];
__device__ int   g_idx [BB*(KA+KM+KS)];
__device__ float g_xg  [M2*DIM];
__device__ float g_xn2 [M2*DIM];
__device__ float g_h   [(size_t)M2*MLP];

__device__ __forceinline__ float tf32_rn(float x) {
    uint32_t u; asm("cvt.rna.tf32.f32 %0, %1;" : "=r"(u) : "f"(x));
    return __uint_as_float(u);
}
__device__ __forceinline__ void mma8(float* c, const uint32_t* a, const uint32_t* b) {
    asm volatile("mma.sync.aligned.m16n8k8.row.col.f32.tf32.tf32.f32 "
        "{%0,%1,%2,%3}, {%4,%5,%6,%7}, {%8,%9}, {%0,%1,%2,%3};\n"
        : "+f"(c[0]), "+f"(c[1]), "+f"(c[2]), "+f"(c[3])
        : "r"(a[0]), "r"(a[1]), "r"(a[2]), "r"(a[3]), "r"(b[0]), "r"(b[1]));
}

// ---------------- LayerNorm ----------------
__global__ void ln_kernel(const float* __restrict__ in, const float* __restrict__ g,
                          const float* __restrict__ bta, float* __restrict__ out) {
    int r = blockIdx.x, t = threadIdx.x;
    const float* xr = in + (size_t)r * DIM;
    float a = xr[t], c = xr[t + 256];
    __shared__ float rs[256], rq[256];
    rs[t] = a + c; rq[t] = a*a + c*c;
    __syncthreads();
    for (int st = 128; st > 0; st >>= 1) {
        if (t < st) { rs[t] += rs[t+st]; rq[t] += rq[t+st]; }
        __syncthreads();
    }
    float mu  = rs[0] * (1.0f/512.0f);
    float var = rq[0] * (1.0f/512.0f) - mu*mu;
    float inv = rsqrtf(var + 1e-5f);
    out[(size_t)r*DIM + t]       = (a - mu) * inv * g[t]     + bta[t];
    out[(size_t)r*DIM + t + 256] = (c - mu) * inv * g[t+256] + bta[t+256];
}

// ---------------- fp32 SGEMM (proven numerics) with ldc ----------------
__global__ void gemm_f32(const float* __restrict__ A, const float* __restrict__ Bw,
                         float* __restrict__ C, int M, int Nc, int K, int ldc) {
    const int BK = 8;
    __shared__ float As[BK][128];
    __shared__ float Bs[BK][128];
    int bm = blockIdx.y * 128, bn = blockIdx.x * 128;
    int tid = threadIdx.x;
    int tx = tid & 15, ty = tid >> 4;
    int lr = tid >> 1, lc = (tid & 1) * 4;

    float acc[8][8];
#pragma unroll
    for (int i = 0; i < 8; i++)
#pragma unroll
        for (int j = 0; j < 8; j++) acc[i][j] = 0.f;

    for (int k0 = 0; k0 < K; k0 += BK) {
        int gr = bm + lr;
        float4 a4 = make_float4(0.f,0.f,0.f,0.f);
        if (gr < M) a4 = *reinterpret_cast<const float4*>(&A[(size_t)gr*K + k0 + lc]);
        As[lc+0][lr] = a4.x; As[lc+1][lr] = a4.y; As[lc+2][lr] = a4.z; As[lc+3][lr] = a4.w;
        int gn = bn + lr;
        float4 b4 = *reinterpret_cast<const float4*>(&Bw[(size_t)gn*K + k0 + lc]);
        Bs[lc+0][lr] = b4.x; Bs[lc+1][lr] = b4.y; Bs[lc+2][lr] = b4.z; Bs[lc+3][lr] = b4.w;
        __syncthreads();
#pragma unroll
        for (int k = 0; k < BK; k++) {
            float4 a0 = *reinterpret_cast<const float4*>(&As[k][ty*8]);
            float4 a1 = *reinterpret_cast<const float4*>(&As[k][ty*8+4]);
            float4 b0 = *reinterpret_cast<const float4*>(&Bs[k][tx*8]);
            float4 b1 = *reinterpret_cast<const float4*>(&Bs[k][tx*8+4]);
            float av[8] = {a0.x,a0.y,a0.z,a0.w,a1.x,a1.y,a1.z,a1.w};
            float bv[8] = {b0.x,b0.y,b0.z,b0.w,b1.x,b1.y,b1.z,b1.w};
#pragma unroll
            for (int i = 0; i < 8; i++)
#pragma unroll
                for (int j = 0; j < 8; j++) acc[i][j] += av[i]*bv[j];
        }
        __syncthreads();
    }
#pragma unroll
    for (int i = 0; i < 8; i++) {
        int row = bm + ty*8 + i;
        if (row >= M) continue;
#pragma unroll
        for (int j = 0; j < 8; j++)
            C[(size_t)row*ldc + bn + tx*8 + j] = acc[i][j];
    }
}

// ---------------- exact q0 for cls tokens ----------------
__global__ void q0_exact(const float* __restrict__ Wq) {
    int b = blockIdx.x, d = threadIdx.x;
    __shared__ float xr[512];
    xr[d] = g_xn[((size_t)b*NN)*DIM + d];
    __syncthreads();
    const float* wr = Wq + (size_t)d*DIM;
    float s = 0.f;
#pragma unroll 4
    for (int c = 0; c < 512; c += 4) {
        float4 w4 = *reinterpret_cast<const float4*>(&wr[c]);
        float4 x4 = *reinterpret_cast<const float4*>(&xr[c]);
        s = fmaf(w4.x, x4.x, s);
        s = fmaf(w4.y, x4.y, s);
        s = fmaf(w4.z, x4.z, s);
        s = fmaf(w4.w, x4.w, s);
    }
    g_qkv[(size_t)b*NN*TDIM + d] = s;
}

// ---------------- TF32 MMA GEMM with ldc ----------------
#define GTS (128*20)
template<int EPI>
__device__ __forceinline__ float epi_f(float v, const float* bias, const float* res,
                                       size_t row, int col, int ldc) {
    if (EPI == 1) v += bias[col] + res[row*(size_t)ldc + col];
    if (EPI == 2) { v += bias[col]; v = 0.5f*v*(1.0f + erff(v*0.70710678118654752f)); }
    return v;
}
__device__ __forceinline__ void cvt_store4(float* hi, int idx, float4 v) {
    *(float4*)&hi[idx] = make_float4(tf32_rn(v.x), tf32_rn(v.y), tf32_rn(v.z), tf32_rn(v.w));
}

template<int EPI>
__global__ void __launch_bounds__(256) gemm_mma(
    const float* __restrict__ A, const float* __restrict__ Bw,
    const float* __restrict__ bias, const float* __restrict__ res,
    float* __restrict__ C, int M, int Nc, int K, int ldc)
{
    extern __shared__ float sm[];
    float* Ah = sm;
    float* Bh = sm + 2*GTS;

    int tid = threadIdx.x;
    int bm = blockIdx.y*128, bn = blockIdx.x*128;
    int lane = tid & 31, g = lane >> 2, tg = lane & 3;
    int warp = tid >> 5;
    int wm = (warp & 1) * 64, wn = (warp >> 1) * 32;

    int r0 = tid >> 2;
    int c0 = (tid & 3) * 4;
    bool v0 = (bm + r0) < M;
    bool v1 = (bm + r0 + 64) < M;
    const float* Ag0 = A  + (size_t)(bm + r0)      * K + c0;
    const float* Ag1 = A  + (size_t)(bm + r0 + 64) * K + c0;
    const float* Bg0 = Bw + (size_t)(bn + r0)      * K + c0;
    const float* Bg1 = Bw + (size_t)(bn + r0 + 64) * K + c0;

    float acc[4][4][4];
#pragma unroll
    for (int i = 0; i < 4; i++)
#pragma unroll
        for (int j = 0; j < 4; j++)
#pragma unroll
            for (int e = 0; e < 4; e++) acc[i][j][e] = 0.f;

    const float4 z4 = make_float4(0.f,0.f,0.f,0.f);
    cvt_store4(Ah, r0*20 + c0,      v0 ? *(const float4*)Ag0 : z4);
    cvt_store4(Ah, (r0+64)*20 + c0, v1 ? *(const float4*)Ag1 : z4);
    cvt_store4(Bh, r0*20 + c0,      *(const float4*)Bg0);
    cvt_store4(Bh, (r0+64)*20 + c0, *(const float4*)Bg1);
    __syncthreads();

    int KT = K >> 4;
    for (int kt = 0; kt < KT; kt++) {
        int buf = kt & 1;
        bool more = (kt + 1) < KT;
        float4 na0, na1, nb0, nb1;
        if (more) {
            int ko = (kt + 1) * 16;
            na0 = v0 ? *(const float4*)(Ag0 + ko) : z4;
            na1 = v1 ? *(const float4*)(Ag1 + ko) : z4;
            nb0 = *(const float4*)(Bg0 + ko);
            nb1 = *(const float4*)(Bg1 + ko);
        }
        const float* As = Ah + buf*GTS;
        const float* Bs = Bh + buf*GTS;
#pragma unroll
        for (int ks = 0; ks < 2; ks++) {
            int kb = ks*8 + tg;
            uint32_t af[4][4], bf[4][2];
#pragma unroll
            for (int i = 0; i < 4; i++) {
                int r = wm + i*16 + g;
                af[i][0] = __float_as_uint(As[r*20 + kb]);
                af[i][1] = __float_as_uint(As[(r+8)*20 + kb]);
                af[i][2] = __float_as_uint(As[r*20 + kb + 4]);
                af[i][3] = __float_as_uint(As[(r+8)*20 + kb + 4]);
            }
#pragma unroll
            for (int j = 0; j < 4; j++) {
                int n = wn + j*8 + g;
                bf[j][0] = __float_as_uint(Bs[n*20 + kb]);
                bf[j][1] = __float_as_uint(Bs[n*20 + kb + 4]);
            }
#pragma unroll
            for (int i = 0; i < 4; i++)
#pragma unroll
                for (int j = 0; j < 4; j++) mma8(acc[i][j], af[i], bf[j]);
        }
        if (more) {
            int nb2 = (buf ^ 1) * GTS;
            cvt_store4(Ah, nb2 + r0*20 + c0,      na0);
            cvt_store4(Ah, nb2 + (r0+64)*20 + c0, na1);
            cvt_store4(Bh, nb2 + r0*20 + c0,      nb0);
            cvt_store4(Bh, nb2 + (r0+64)*20 + c0, nb1);
            __syncthreads();
        }
    }

#pragma unroll
    for (int i = 0; i < 4; i++) {
        int rr0 = bm + wm + i*16 + g;
        int rr1 = rr0 + 8;
#pragma unroll
        for (int j = 0; j < 4; j++) {
            int c = bn + wn + j*8 + tg*2;
            if (rr0 < M) {
                C[(size_t)rr0*ldc + c  ] = epi_f<EPI>(acc[i][j][0], bias, res, rr0, c,   ldc);
                C[(size_t)rr0*ldc + c+1] = epi_f<EPI>(acc[i][j][1], bias, res, rr0, c+1, ldc);
            }
            if (rr1 < M) {
                C[(size_t)rr1*ldc + c  ] = epi_f<EPI>(acc[i][j][2], bias, res, rr1, c,   ldc);
                C[(size_t)rr1*ldc + c+1] = epi_f<EPI>(acc[i][j][3], bias, res, rr1, c+1, ldc);
            }
        }
    }
}

// ---------------- fused attention: R4-proven fp32, 4 queries/iter ----------------
__global__ void __launch_bounds__(256) attn_kernel(const float* __restrict__ mask) {
    extern __shared__ float dyn[];
    float* Ks   = dyn;
    float* Vs   = Ks + NN*68;
    float* sc   = Vs + NN*68;
    float* q4   = sc + 4*388;
    float* wred = q4 + 256;
    float* bmax = wred + 32;
    float* binv = bmax + 4;
    float* part = binv + 4;

    int bh = blockIdx.x, b = bh >> 3, h = bh & 7;
    int t = threadIdx.x, lane = t & 31, w = t >> 5;
    const float* qkvb = g_qkv + (size_t)b * NN * TDIM;

    for (int i = t; i < NN*16; i += 256) {
        int m = i >> 4, d4 = (i & 15) * 4;
        *(float4*)&Ks[m*68 + d4] = *(const float4*)&qkvb[(size_t)m*TDIM + DIM   + h*HD + d4];
        *(float4*)&Vs[m*68 + d4] = *(const float4*)&qkvb[(size_t)m*TDIM + 2*DIM + h*HD + d4];
    }
    __syncthreads();

    const float addc = 1e-6f / 385.0f;
    const float* mb = mask + (size_t)b * NN * NN;

    for (int n0 = 0; n0 < NN; n0 += 4) {
        {
            int q = t >> 6, d = t & 63;
            int nq = n0 + q; if (nq > NN-1) nq = NN-1;
            q4[q*64 + d] = qkvb[(size_t)nq*TDIM + h*HD + d];
        }
        __syncthreads();

        float lm0=-1e30f, lm1=-1e30f, lm2=-1e30f, lm3=-1e30f;
        for (int m = t; m < NN; m += 256) {
            float s0=0.f, s1=0.f, s2=0.f, s3=0.f;
#pragma unroll
            for (int d4 = 0; d4 < 64; d4 += 4) {
                float4 k  = *(float4*)&Ks[m*68 + d4];
                float4 qa = *(float4*)&q4[d4];
                float4 qb = *(float4*)&q4[64 + d4];
                float4 qc = *(float4*)&q4[128 + d4];
                float4 qd = *(float4*)&q4[192 + d4];
                s0 += k.x*qa.x + k.y*qa.y + k.z*qa.z + k.w*qa.w;
                s1 += k.x*qb.x + k.y*qb.y + k.z*qb.z + k.w*qb.w;
                s2 += k.x*qc.x + k.y*qc.y + k.z*qc.z + k.w*qc.w;
                s3 += k.x*qd.x + k.y*qd.y + k.z*qd.z + k.w*qd.w;
            }
            s0 *= 0.125f; s1 *= 0.125f; s2 *= 0.125f; s3 *= 0.125f;
            sc[m] = s0; sc[388+m] = s1; sc[776+m] = s2; sc[1164+m] = s3;
            lm0 = fmaxf(lm0, s0); lm1 = fmaxf(lm1, s1);
            lm2 = fmaxf(lm2, s2); lm3 = fmaxf(lm3, s3);
        }
#pragma unroll
        for (int off = 16; off; off >>= 1) {
            lm0 = fmaxf(lm0, __shfl_xor_sync(0xFFFFFFFFu, lm0, off));
            lm1 = fmaxf(lm1, __shfl_xor_sync(0xFFFFFFFFu, lm1, off));
            lm2 = fmaxf(lm2, __shfl_xor_sync(0xFFFFFFFFu, lm2, off));
            lm3 = fmaxf(lm3, __shfl_xor_sync(0xFFFFFFFFu, lm3, off));
        }
        if (lane == 0) { wred[w*4+0]=lm0; wred[w*4+1]=lm1; wred[w*4+2]=lm2; wred[w*4+3]=lm3; }
        __syncthreads();
        if (t < 4) {
            float v = wred[t];
#pragma unroll
            for (int wi = 1; wi < 8; wi++) v = fmaxf(v, wred[wi*4 + t]);
            bmax[t] = v;
        }
        __syncthreads();

        float ls0=0.f, ls1=0.f, ls2=0.f, ls3=0.f;
        float bm0=bmax[0], bm1=bmax[1], bm2=bmax[2], bm3=bmax[3];
        int nq1 = (n0+1 < NN) ? n0+1 : NN-1;
        int nq2 = (n0+2 < NN) ? n0+2 : NN-1;
        int nq3 = (n0+3 < NN) ? n0+3 : NN-1;
        const float* mr0 = mb + (size_t)n0  * NN;
        const float* mr1 = mb + (size_t)nq1 * NN;
        const float* mr2 = mb + (size_t)nq2 * NN;
        const float* mr3 = mb + (size_t)nq3 * NN;
        if (n0 == 0) {
            // cls row (plane 0) needs exact expf for the top-k chain
            for (int m = t; m < NN; m += 256) {
                float e0 = expf(sc[m]       - bm0) * mr0[m];
                float e1 = __expf(sc[388+m]  - bm1) * mr1[m];
                float e2 = __expf(sc[776+m]  - bm2) * mr2[m];
                float e3 = __expf(sc[1164+m] - bm3) * mr3[m];
                sc[m] = e0; sc[388+m] = e1; sc[776+m] = e2; sc[1164+m] = e3;
                ls0 += e0; ls1 += e1; ls2 += e2; ls3 += e3;
            }
        } else {
            for (int m = t; m < NN; m += 256) {
                float e0 = __expf(sc[m]      - bm0) * mr0[m];
                float e1 = __expf(sc[388+m]  - bm1) * mr1[m];
                float e2 = __expf(sc[776+m]  - bm2) * mr2[m];
                float e3 = __expf(sc[1164+m] - bm3) * mr3[m];
                sc[m] = e0; sc[388+m] = e1; sc[776+m] = e2; sc[1164+m] = e3;
                ls0 += e0; ls1 += e1; ls2 += e2; ls3 += e3;
            }
        }
#pragma unroll
        for (int off = 16; off; off >>= 1) {
            ls0 += __shfl_xor_sync(0xFFFFFFFFu, ls0, off);
            ls1 += __shfl_xor_sync(0xFFFFFFFFu, ls1, off);
            ls2 += __shfl_xor_sync(0xFFFFFFFFu, ls2, off);
            ls3 += __shfl_xor_sync(0xFFFFFFFFu, ls3, off);
        }
        if (lane == 0) { wred[w*4+0]=ls0; wred[w*4+1]=ls1; wred[w*4+2]=ls2; wred[w*4+3]=ls3; }
        __syncthreads();
        if (t < 4) {
            float s = 0.f;
#pragma unroll
            for (int wi = 0; wi < 8; wi++) s += wred[wi*4 + t];
            binv[t] = 1.0f / (s + 1e-6f);
        }
        __syncthreads();

        if (n0 == 0) {
            float iv = binv[0];
            for (int j = t; j < 384; j += 256)
                g_clsP[((size_t)b*HH + h)*384 + j] = (sc[1+j] + addc) * iv * 0.125f;
        }

        {
            int dd = lane * 2;
            float iv0=binv[0], iv1=binv[1], iv2=binv[2], iv3=binv[3];
            float ax0=0,ay0=0, ax1=0,ay1=0, ax2=0,ay2=0, ax3=0,ay3=0;
            for (int m = w; m < NN; m += 8) {
                float2 v = *(float2*)&Vs[m*68 + dd];
                float p0 = (sc[m]      + addc) * iv0;
                float p1 = (sc[388+m]  + addc) * iv1;
                float p2 = (sc[776+m]  + addc) * iv2;
                float p3 = (sc[1164+m] + addc) * iv3;
                ax0 += p0*v.x; ay0 += p0*v.y;
                ax1 += p1*v.x; ay1 += p1*v.y;
                ax2 += p2*v.x; ay2 += p2*v.y;
                ax3 += p3*v.x; ay3 += p3*v.y;
            }
            int base = (w*4)*64 + dd;
            part[base      ] = ax0; part[base + 1  ] = ay0;
            part[base + 64 ] = ax1; part[base + 65 ] = ay1;
            part[base + 128] = ax2; part[base + 129] = ay2;
            part[base + 192] = ax3; part[base + 193] = ay3;
        }
        __syncthreads();
        {
            int q = t >> 6, d = t & 63;
            int n = n0 + q;
            if (n < NN) {
                float s = 0.f;
#pragma unroll
                for (int sp = 0; sp < 8; sp++) s += part[(sp*4 + q)*64 + d];
                g_xatt[((size_t)(b*NN + n))*DIM + h*HD + d] = s;
            }
        }
        __syncthreads();
    }
}

// ---------------- cls reduce ----------------
__global__ void cls_reduce_kernel() {
    int i = blockIdx.x*256 + threadIdx.x;
    if (i < BB*384) {
        int b = i / 384, j = i % 384;
        float s = 0.f;
#pragma unroll
        for (int h = 0; h < HH; h++) s += g_clsP[((size_t)b*HH + h)*384 + j];
        g_cls[i] = s;
    }
}

// ---------------- top-k (exact jax tie semantics) ----------------
__global__ void topk_kernel(float* __restrict__ out) {
    const int nsz_[3]  = {64, 192, 128};
    const int kk_[3]   = {KA, KM, KS};
    const int base_[3] = {0, 64, 256};
    const int ib_[3]   = {0, KA, KA+KM};
    const long long ob_[3] = {OFF_IA, OFF_IM, OFF_IS};
    const int os_[3]   = {KA, KM, KS};

    int b = blockIdx.x / 3, g = blockIdx.x % 3;
    int nsz = nsz_[g], kk = kk_[g];
    __shared__ float v[192];
    __shared__ float rv[256];
    __shared__ int   ri[256];
    int t = threadIdx.x;
    if (t < nsz) v[t] = g_cls[b*384 + base_[g] + t];
    __syncthreads();

    for (int i = 0; i < kk; i++) {
        rv[t] = (t < nsz) ? v[t] : -INFINITY;
        ri[t] = t;
        __syncthreads();
        for (int s = 128; s > 0; s >>= 1) {
            if (t < s) {
                float v2 = rv[t+s]; int i2 = ri[t+s];
                if (v2 > rv[t] || (v2 == rv[t] && i2 < ri[t])) { rv[t] = v2; ri[t] = i2; }
            }
            __syncthreads();
        }
        if (t == 0) {
            int wn = ri[0];
            g_idx[b*(KA+KM+KS) + ib_[g] + i] = wn;
            out[ob_[g] + (long long)b*os_[g] + i] = (float)wn;
            v[wn] = -INFINITY;
        }
        __syncthreads();
    }
}

// ---------------- gather ----------------
__global__ void gather_kernel() {
    int r = blockIdx.x;
    int b = r / RN, p = r % RN;
    int s;
    if (p == 0)            s = 0;
    else if (p < 1+KA)     s = 1   + g_idx[b*(KA+KM+KS) + (p-1)];
    else if (p < 1+KA+KM)  s = 65  + g_idx[b*(KA+KM+KS) + KA + (p-1-KA)];
    else                   s = 257 + g_idx[b*(KA+KM+KS) + KA+KM + (p-1-KA-KM)];
    const float4* src = reinterpret_cast<const float4*>(g_xres + ((size_t)(b*NN + s))*DIM);
    float4* dst = reinterpret_cast<float4*>(g_xg + (size_t)r*DIM);
    dst[threadIdx.x] = src[threadIdx.x];
}

// ---------------- mask = ones (vectorized) ----------------
__global__ void mask_fill_kernel(float* __restrict__ out) {
    long long i = (long long)blockIdx.x*256 + threadIdx.x;
    if (i < MASK_SZ/4) {
        float4* o = reinterpret_cast<float4*>(out + OFF_MASK);
        o[i] = make_float4(1.f,1.f,1.f,1.f);
    }
}

// ---------------- launcher ----------------
extern "C" void kernel_launch(void* const* d_in, const int* in_sizes, int n_in,
                              void* d_out, int out_size) {
    const float* x     = (const float*)d_in[0];
    const float* amask = (const float*)d_in[1];
    const float* Wqkv  = (const float*)d_in[5];
    const float* Wproj = (const float*)d_in[6];
    const float* bproj = (const float*)d_in[7];
    const float* g1    = (const float*)d_in[8];
    const float* b1    = (const float*)d_in[9];
    const float* g2    = (const float*)d_in[10];
    const float* b2    = (const float*)d_in[11];
    const float* Wfc1  = (const float*)d_in[12];
    const float* bfc1  = (const float*)d_in[13];
    const float* Wfc2  = (const float*)d_in[14];
    const float* bfc2  = (const float*)d_in[15];
    float* out = (float*)d_out;

    float *p_xn, *p_qkv, *p_xatt, *p_xres, *p_xg, *p_xn2, *p_h;
    cudaGetSymbolAddress((void**)&p_xn,   g_xn);
    cudaGetSymbolAddress((void**)&p_qkv,  g_qkv);
    cudaGetSymbolAddress((void**)&p_xatt, g_xatt);
    cudaGetSymbolAddress((void**)&p_xres, g_xres);
    cudaGetSymbolAddress((void**)&p_xg,   g_xg);
    cudaGetSymbolAddress((void**)&p_xn2,  g_xn2);
    cudaGetSymbolAddress((void**)&p_h,    g_h);

    const int SMEM_S = 4*GTS*4;                              // 40960 B
    const int ATTN_SMEM = (2*NN*68 + 4*388 + 256 + 32 + 8 + 2048) * 4;  // ~200KB
    static int init_done = 0;
    if (!init_done) {
        cudaFuncSetAttribute(gemm_mma<0>, cudaFuncAttributeMaxDynamicSharedMemorySize, SMEM_S);
        cudaFuncSetAttribute(gemm_mma<1>, cudaFuncAttributeMaxDynamicSharedMemorySize, SMEM_S);
        cudaFuncSetAttribute(gemm_mma<2>, cudaFuncAttributeMaxDynamicSharedMemorySize, SMEM_S);
        cudaFuncSetAttribute(attn_kernel, cudaFuncAttributeMaxDynamicSharedMemorySize, ATTN_SMEM);
        init_done = 1;
    }

    ln_kernel<<<M1, 256>>>(x, g1, b1, p_xn);
    // Q (tf32), V (tf32), K (fp32 exact), q0 (fp32 exact)
    gemm_mma<0><<<dim3(4, (M1+127)/128), 256, SMEM_S>>>(p_xn, Wqkv,            nullptr, nullptr, p_qkv,        M1, 512, DIM, TDIM);
    gemm_mma<0><<<dim3(4, (M1+127)/128), 256, SMEM_S>>>(p_xn, Wqkv + 1024*512, nullptr, nullptr, p_qkv + 1024, M1, 512, DIM, TDIM);
    gemm_f32<<<dim3(4, (M1+127)/128), 256>>>(p_xn, Wqkv + 512*512, p_qkv + 512, M1, 512, DIM, TDIM);
    q0_exact<<<BB, 512>>>(Wqkv);
    attn_kernel<<<BB*HH, 256, ATTN_SMEM>>>(amask);
    gemm_mma<1><<<dim3(DIM/128, (M1+127)/128), 256, SMEM_S>>>(p_xatt, Wproj, bproj, x, p_xres, M1, DIM, DIM, DIM);
    cls_reduce_kernel<<<(BB*384 + 255)/256, 256>>>();
    topk_kernel<<<BB*3, 256>>>(out);
    gather_kernel<<<M2, 128>>>();
    mask_fill_kernel<<<(int)((MASK_SZ/4 + 255)/256), 256>>>(out);
    ln_kernel<<<M2, 256>>>(p_xg, g2, b2, p_xn2);
    gemm_mma<2><<<dim3(MLP/128, (M2+127)/128), 256, SMEM_S>>>(p_xn2, Wfc1, bfc1, nullptr, p_h, M2, MLP, DIM, MLP);
    gemm_mma<1><<<dim3(DIM/128, (M2+127)/128), 256, SMEM_S>>>(p_h, Wfc2, bfc2, p_xg, out, M2, DIM, MLP, DIM);
}

// round 7
// speedup vs baseline: 1.4307x; 1.2976x over previous
#include <cuda_runtime.h>
#include <math.h>
#include <stdint.h>

#define BB 32
#define NN 385
#define DIM 512
#define HH 8
#define HD 64
#define TDIM 1536
#define MLP 2048
#define KA 45
#define KM 135
#define KS 90
#define RN 271
#define M1 (BB*NN)
#define M2 (BB*RN)

#define X_SZ   ((long long)BB*RN*DIM)
#define OFF_IA (X_SZ)
#define OFF_IM (OFF_IA + (long long)BB*KA)
#define OFF_IS (OFF_IM + (long long)BB*KM)
#define OFF_MASK (OFF_IS + (long long)BB*KS)
#define MASK_SZ ((long long)BB*RN*RN)

__device__ float g_xn  [M1*DIM];
__device__ float g_qkv [(size_t)M1*TDIM];
__device__ float g_xatt[M1*DIM];
__device__ float g_xres[M1*DIM];
__device__ float g_clsP[BB*HH*384];
__device__ float g_cls [BB*384];
__device__ int   g_idx [BB*(KA+KM+KS)];
__device__ float g_xg  [M2*DIM];
__device__ float g_xn2 [M2*DIM];
__device__ float g_h   [(size_t)M2*MLP];

__device__ __forceinline__ float tf32_rn(float x) {
    uint32_t u; asm("cvt.rna.tf32.f32 %0, %1;" : "=r"(u) : "f"(x));
    return __uint_as_float(u);
}
__device__ __forceinline__ void mma8(float* c, const uint32_t* a, const uint32_t* b) {
    asm volatile("mma.sync.aligned.m16n8k8.row.col.f32.tf32.tf32.f32 "
        "{%0,%1,%2,%3}, {%4,%5,%6,%7}, {%8,%9}, {%0,%1,%2,%3};\n"
        : "+f"(c[0]), "+f"(c[1]), "+f"(c[2]), "+f"(c[3])
        : "r"(a[0]), "r"(a[1]), "r"(a[2]), "r"(a[3]), "r"(b[0]), "r"(b[1]));
}

// ---------------- LayerNorm ----------------
__global__ void ln_kernel(const float* __restrict__ in, const float* __restrict__ g,
                          const float* __restrict__ bta, float* __restrict__ out) {
    int r = blockIdx.x, t = threadIdx.x;
    const float* xr = in + (size_t)r * DIM;
    float a = xr[t], c = xr[t + 256];
    __shared__ float rs[256], rq[256];
    rs[t] = a + c; rq[t] = a*a + c*c;
    __syncthreads();
    for (int st = 128; st > 0; st >>= 1) {
        if (t < st) { rs[t] += rs[t+st]; rq[t] += rq[t+st]; }
        __syncthreads();
    }
    float mu  = rs[0] * (1.0f/512.0f);
    float var = rq[0] * (1.0f/512.0f) - mu*mu;
    float inv = rsqrtf(var + 1e-5f);
    out[(size_t)r*DIM + t]       = (a - mu) * inv * g[t]     + bta[t];
    out[(size_t)r*DIM + t + 256] = (c - mu) * inv * g[t+256] + bta[t+256];
}

// ---------------- fp32 SGEMM (proven numerics) with ldc ----------------
__global__ void gemm_f32(const float* __restrict__ A, const float* __restrict__ Bw,
                         float* __restrict__ C, int M, int Nc, int K, int ldc) {
    const int BK = 8;
    __shared__ float As[BK][128];
    __shared__ float Bs[BK][128];
    int bm = blockIdx.y * 128, bn = blockIdx.x * 128;
    int tid = threadIdx.x;
    int tx = tid & 15, ty = tid >> 4;
    int lr = tid >> 1, lc = (tid & 1) * 4;

    float acc[8][8];
#pragma unroll
    for (int i = 0; i < 8; i++)
#pragma unroll
        for (int j = 0; j < 8; j++) acc[i][j] = 0.f;

    for (int k0 = 0; k0 < K; k0 += BK) {
        int gr = bm + lr;
        float4 a4 = make_float4(0.f,0.f,0.f,0.f);
        if (gr < M) a4 = *reinterpret_cast<const float4*>(&A[(size_t)gr*K + k0 + lc]);
        As[lc+0][lr] = a4.x; As[lc+1][lr] = a4.y; As[lc+2][lr] = a4.z; As[lc+3][lr] = a4.w;
        int gn = bn + lr;
        float4 b4 = *reinterpret_cast<const float4*>(&Bw[(size_t)gn*K + k0 + lc]);
        Bs[lc+0][lr] = b4.x; Bs[lc+1][lr] = b4.y; Bs[lc+2][lr] = b4.z; Bs[lc+3][lr] = b4.w;
        __syncthreads();
#pragma unroll
        for (int k = 0; k < BK; k++) {
            float4 a0 = *reinterpret_cast<const float4*>(&As[k][ty*8]);
            float4 a1 = *reinterpret_cast<const float4*>(&As[k][ty*8+4]);
            float4 b0 = *reinterpret_cast<const float4*>(&Bs[k][tx*8]);
            float4 b1 = *reinterpret_cast<const float4*>(&Bs[k][tx*8+4]);
            float av[8] = {a0.x,a0.y,a0.z,a0.w,a1.x,a1.y,a1.z,a1.w};
            float bv[8] = {b0.x,b0.y,b0.z,b0.w,b1.x,b1.y,b1.z,b1.w};
#pragma unroll
            for (int i = 0; i < 8; i++)
#pragma unroll
                for (int j = 0; j < 8; j++) acc[i][j] += av[i]*bv[j];
        }
        __syncthreads();
    }
#pragma unroll
    for (int i = 0; i < 8; i++) {
        int row = bm + ty*8 + i;
        if (row >= M) continue;
#pragma unroll
        for (int j = 0; j < 8; j++)
            C[(size_t)row*ldc + bn + tx*8 + j] = acc[i][j];
    }
}

// ---------------- exact q0 for cls tokens ----------------
__global__ void q0_exact(const float* __restrict__ Wq) {
    int b = blockIdx.x, d = threadIdx.x;
    __shared__ float xr[512];
    xr[d] = g_xn[((size_t)b*NN)*DIM + d];
    __syncthreads();
    const float* wr = Wq + (size_t)d*DIM;
    float s = 0.f;
#pragma unroll 4
    for (int c = 0; c < 512; c += 4) {
        float4 w4 = *reinterpret_cast<const float4*>(&wr[c]);
        float4 x4 = *reinterpret_cast<const float4*>(&xr[c]);
        s = fmaf(w4.x, x4.x, s);
        s = fmaf(w4.y, x4.y, s);
        s = fmaf(w4.z, x4.z, s);
        s = fmaf(w4.w, x4.w, s);
    }
    g_qkv[(size_t)b*NN*TDIM + d] = s;
}

// ---------------- TF32 MMA GEMM with ldc ----------------
#define GTS (128*20)
template<int EPI>
__device__ __forceinline__ float epi_f(float v, const float* bias, const float* res,
                                       size_t row, int col, int ldc) {
    if (EPI == 1) v += bias[col] + res[row*(size_t)ldc + col];
    if (EPI == 2) { v += bias[col]; v = 0.5f*v*(1.0f + erff(v*0.70710678118654752f)); }
    return v;
}
__device__ __forceinline__ void cvt_store4(float* hi, int idx, float4 v) {
    *(float4*)&hi[idx] = make_float4(tf32_rn(v.x), tf32_rn(v.y), tf32_rn(v.z), tf32_rn(v.w));
}

template<int EPI>
__global__ void __launch_bounds__(256) gemm_mma(
    const float* __restrict__ A, const float* __restrict__ Bw,
    const float* __restrict__ bias, const float* __restrict__ res,
    float* __restrict__ C, int M, int Nc, int K, int ldc)
{
    extern __shared__ float sm[];
    float* Ah = sm;
    float* Bh = sm + 2*GTS;

    int tid = threadIdx.x;
    int bm = blockIdx.y*128, bn = blockIdx.x*128;
    int lane = tid & 31, g = lane >> 2, tg = lane & 3;
    int warp = tid >> 5;
    int wm = (warp & 1) * 64, wn = (warp >> 1) * 32;

    int r0 = tid >> 2;
    int c0 = (tid & 3) * 4;
    bool v0 = (bm + r0) < M;
    bool v1 = (bm + r0 + 64) < M;
    const float* Ag0 = A  + (size_t)(bm + r0)      * K + c0;
    const float* Ag1 = A  + (size_t)(bm + r0 + 64) * K + c0;
    const float* Bg0 = Bw + (size_t)(bn + r0)      * K + c0;
    const float* Bg1 = Bw + (size_t)(bn + r0 + 64) * K + c0;

    float acc[4][4][4];
#pragma unroll
    for (int i = 0; i < 4; i++)
#pragma unroll
        for (int j = 0; j < 4; j++)
#pragma unroll
            for (int e = 0; e < 4; e++) acc[i][j][e] = 0.f;

    const float4 z4 = make_float4(0.f,0.f,0.f,0.f);
    cvt_store4(Ah, r0*20 + c0,      v0 ? *(const float4*)Ag0 : z4);
    cvt_store4(Ah, (r0+64)*20 + c0, v1 ? *(const float4*)Ag1 : z4);
    cvt_store4(Bh, r0*20 + c0,      *(const float4*)Bg0);
    cvt_store4(Bh, (r0+64)*20 + c0, *(const float4*)Bg1);
    __syncthreads();

    int KT = K >> 4;
    for (int kt = 0; kt < KT; kt++) {
        int buf = kt & 1;
        bool more = (kt + 1) < KT;
        float4 na0, na1, nb0, nb1;
        if (more) {
            int ko = (kt + 1) * 16;
            na0 = v0 ? *(const float4*)(Ag0 + ko) : z4;
            na1 = v1 ? *(const float4*)(Ag1 + ko) : z4;
            nb0 = *(const float4*)(Bg0 + ko);
            nb1 = *(const float4*)(Bg1 + ko);
        }
        const float* As = Ah + buf*GTS;
        const float* Bs = Bh + buf*GTS;
#pragma unroll
        for (int ks = 0; ks < 2; ks++) {
            int kb = ks*8 + tg;
            uint32_t af[4][4], bf[4][2];
#pragma unroll
            for (int i = 0; i < 4; i++) {
                int r = wm + i*16 + g;
                af[i][0] = __float_as_uint(As[r*20 + kb]);
                af[i][1] = __float_as_uint(As[(r+8)*20 + kb]);
                af[i][2] = __float_as_uint(As[r*20 + kb + 4]);
                af[i][3] = __float_as_uint(As[(r+8)*20 + kb + 4]);
            }
#pragma unroll
            for (int j = 0; j < 4; j++) {
                int n = wn + j*8 + g;
                bf[j][0] = __float_as_uint(Bs[n*20 + kb]);
                bf[j][1] = __float_as_uint(Bs[n*20 + kb + 4]);
            }
#pragma unroll
            for (int i = 0; i < 4; i++)
#pragma unroll
                for (int j = 0; j < 4; j++) mma8(acc[i][j], af[i], bf[j]);
        }
        if (more) {
            int nb2 = (buf ^ 1) * GTS;
            cvt_store4(Ah, nb2 + r0*20 + c0,      na0);
            cvt_store4(Ah, nb2 + (r0+64)*20 + c0, na1);
            cvt_store4(Bh, nb2 + r0*20 + c0,      nb0);
            cvt_store4(Bh, nb2 + (r0+64)*20 + c0, nb1);
            __syncthreads();
        }
    }

#pragma unroll
    for (int i = 0; i < 4; i++) {
        int rr0 = bm + wm + i*16 + g;
        int rr1 = rr0 + 8;
#pragma unroll
        for (int j = 0; j < 4; j++) {
            int c = bn + wn + j*8 + tg*2;
            if (rr0 < M) {
                C[(size_t)rr0*ldc + c  ] = epi_f<EPI>(acc[i][j][0], bias, res, rr0, c,   ldc);
                C[(size_t)rr0*ldc + c+1] = epi_f<EPI>(acc[i][j][1], bias, res, rr0, c+1, ldc);
            }
            if (rr1 < M) {
                C[(size_t)rr1*ldc + c  ] = epi_f<EPI>(acc[i][j][2], bias, res, rr1, c,   ldc);
                C[(size_t)rr1*ldc + c+1] = epi_f<EPI>(acc[i][j][3], bias, res, rr1, c+1, ldc);
            }
        }
    }
}

// ---------------- tensor-core attention ----------------
// per (b,h) block, 8 warps. Query tiles of 64 rows (7 tiles, rows clamped to 384).
// S tile 64x448 fp32 in smem; K/V streamed from gmem in 64-row tf32 tiles.
// cls row (qt==0,row 0) recomputed bit-identically to the R6 fp32 path.
#define SP 452
#define QP 68
#define W_S   (64*SP)            // 28928
#define W_Q   (64*QP)            // 4352
#define ATTN_WORDS (W_S + 3*W_Q + 392 + 64 + 64 + 8)

__global__ void __launch_bounds__(256) attn_kernel(const float* __restrict__ mask) {
    extern __shared__ float dyn[];
    float* S   = dyn;
    float* Qs  = dyn + W_S;
    float* Ks  = Qs + W_Q;
    float* Vs  = Ks + W_Q;
    float* scE = Vs + W_Q;        // 392
    float* q0f = scE + 392;       // 64
    float* wred= q0f + 64;        // 64

    int bh = blockIdx.x, b = bh >> 3, h = bh & 7;
    int t = threadIdx.x, lane = t & 31, w = t >> 5;
    int g = lane >> 2, tg = lane & 3;
    int wmS = (w >> 1) * 16, wnS = (w & 1) * 32;
    const float* qkvb = g_qkv + (size_t)b * NN * TDIM;
    const float* mb   = mask + (size_t)b * NN * NN;
    const float addc = 1e-6f / 385.0f;

    for (int qt = 0; qt < 7; qt++) {
        int q0r = qt * 64;
        // load Q tile (tf32)
        for (int i = t; i < 64*16; i += 256) {
            int r = i >> 4, d4 = (i & 15) * 4;
            int row = q0r + r; if (row > 384) row = 384;
            cvt_store4(Qs, r*QP + d4, *(const float4*)&qkvb[(size_t)row*TDIM + h*HD + d4]);
        }
        // ---- S = Q K^T over key tiles ----
        for (int kt = 0; kt < 7; kt++) {
            __syncthreads();
            for (int i = t; i < 64*16; i += 256) {
                int r = i >> 4, d4 = (i & 15) * 4;
                int row = kt*64 + r; if (row > 384) row = 384;
                cvt_store4(Ks, r*QP + d4, *(const float4*)&qkvb[(size_t)row*TDIM + DIM + h*HD + d4]);
            }
            __syncthreads();
            float acc[4][4];
#pragma unroll
            for (int j = 0; j < 4; j++)
#pragma unroll
                for (int e = 0; e < 4; e++) acc[j][e] = 0.f;
#pragma unroll
            for (int ks = 0; ks < 8; ks++) {
                int kb = ks*8 + tg;
                uint32_t a[4];
                a[0] = __float_as_uint(Qs[(wmS+g)*QP + kb]);
                a[1] = __float_as_uint(Qs[(wmS+g+8)*QP + kb]);
                a[2] = __float_as_uint(Qs[(wmS+g)*QP + kb + 4]);
                a[3] = __float_as_uint(Qs[(wmS+g+8)*QP + kb + 4]);
#pragma unroll
                for (int j = 0; j < 4; j++) {
                    uint32_t bf[2];
                    int n = wnS + j*8 + g;
                    bf[0] = __float_as_uint(Ks[n*QP + kb]);
                    bf[1] = __float_as_uint(Ks[n*QP + kb + 4]);
                    mma8(acc[j], a, bf);
                }
            }
#pragma unroll
            for (int j = 0; j < 4; j++) {
                int col = kt*64 + wnS + j*8 + tg*2;
                int r0 = wmS + g, r1 = r0 + 8;
                *(float2*)&S[r0*SP + col] = make_float2(acc[j][0]*0.125f, acc[j][1]*0.125f);
                *(float2*)&S[r1*SP + col] = make_float2(acc[j][2]*0.125f, acc[j][3]*0.125f);
            }
        }
        __syncthreads();
        // ---- softmax: warp per row, 8 rows/warp ----
        for (int r8 = 0; r8 < 8; r8++) {
            int row = w*8 + r8;
            int grow = q0r + row; if (grow > 384) grow = 384;
            const float* mrow = mb + (size_t)grow * NN;
            float* Sr = S + row*SP;
            float mx = -1e30f;
            for (int m = lane; m < 385; m += 32) mx = fmaxf(mx, Sr[m]);
#pragma unroll
            for (int off = 16; off; off >>= 1) mx = fmaxf(mx, __shfl_xor_sync(0xFFFFFFFFu, mx, off));
            float sum = 0.f;
            for (int m = lane; m < 385; m += 32) {
                float e = __expf(Sr[m] - mx) * mrow[m];
                Sr[m] = e; sum += e;
            }
#pragma unroll
            for (int off = 16; off; off >>= 1) sum += __shfl_xor_sync(0xFFFFFFFFu, sum, off);
            float iv = 1.0f / (sum + 1e-6f);
            for (int m = lane; m < 448; m += 32)
                Sr[m] = (m < 385) ? tf32_rn((Sr[m] + addc) * iv) : 0.f;
        }
        // ---- exact cls row (qt==0): bit-identical to R6 path ----
        if (qt == 0) {
            if (t < 64) q0f[t] = qkvb[h*HD + t];
            __syncthreads();
            float lm0 = -1e30f;
            const float* kg = qkvb + DIM + h*HD;
            for (int m = t; m < 385; m += 256) {
                float s0 = 0.f;
#pragma unroll
                for (int d4 = 0; d4 < 64; d4 += 4) {
                    float4 k  = *(const float4*)&kg[(size_t)m*TDIM + d4];
                    float4 qa = *(const float4*)&q0f[d4];
                    s0 += k.x*qa.x + k.y*qa.y + k.z*qa.z + k.w*qa.w;
                }
                s0 *= 0.125f;
                scE[m] = s0;
                lm0 = fmaxf(lm0, s0);
            }
#pragma unroll
            for (int off = 16; off; off >>= 1) lm0 = fmaxf(lm0, __shfl_xor_sync(0xFFFFFFFFu, lm0, off));
            if (lane == 0) wred[w] = lm0;
            __syncthreads();
            float bm0 = wred[0];
#pragma unroll
            for (int wi = 1; wi < 8; wi++) bm0 = fmaxf(bm0, wred[wi]);
            float ls0 = 0.f;
            for (int m = t; m < 385; m += 256) {
                float e0 = expf(scE[m] - bm0) * mb[m];
                scE[m] = e0; ls0 += e0;
            }
#pragma unroll
            for (int off = 16; off; off >>= 1) ls0 += __shfl_xor_sync(0xFFFFFFFFu, ls0, off);
            if (lane == 0) wred[32 + w] = ls0;
            __syncthreads();
            float sm0 = 0.f;
#pragma unroll
            for (int wi = 0; wi < 8; wi++) sm0 += wred[32 + wi];
            float iv = 1.0f / (sm0 + 1e-6f);
            for (int j = t; j < 384; j += 256)
                g_clsP[((size_t)b*HH + h)*384 + j] = (scE[1+j] + addc) * iv * 0.125f;
            for (int m = t; m < 385; m += 256)
                S[m] = tf32_rn((scE[m] + addc) * iv);
        }
        __syncthreads();
        // ---- O = W V over key tiles ----
        float oacc[4][4];
#pragma unroll
        for (int j = 0; j < 4; j++)
#pragma unroll
            for (int e = 0; e < 4; e++) oacc[j][e] = 0.f;
        for (int kt = 0; kt < 7; kt++) {
            __syncthreads();
            for (int i = t; i < 64*16; i += 256) {
                int r = i >> 4, d4 = (i & 15) * 4;
                int row = kt*64 + r; if (row > 384) row = 384;
                cvt_store4(Vs, r*QP + d4, *(const float4*)&qkvb[(size_t)row*TDIM + 2*DIM + h*HD + d4]);
            }
            __syncthreads();
#pragma unroll
            for (int ks = 0; ks < 8; ks++) {
                int lk = ks*8 + tg;
                int kb = kt*64 + lk;
                uint32_t a[4];
                a[0] = __float_as_uint(S[(wmS+g)*SP + kb]);
                a[1] = __float_as_uint(S[(wmS+g+8)*SP + kb]);
                a[2] = __float_as_uint(S[(wmS+g)*SP + kb + 4]);
                a[3] = __float_as_uint(S[(wmS+g+8)*SP + kb + 4]);
#pragma unroll
                for (int j = 0; j < 4; j++) {
                    uint32_t bf[2];
                    int n = wnS + j*8 + g;
                    bf[0] = __float_as_uint(Vs[lk*QP + n]);
                    bf[1] = __float_as_uint(Vs[(lk+4)*QP + n]);
                    mma8(oacc[j], a, bf);
                }
            }
        }
        // store output
        {
            int r0g = q0r + wmS + g, r1g = r0g + 8;
#pragma unroll
            for (int j = 0; j < 4; j++) {
                int col = wnS + j*8 + tg*2;
                if (r0g < NN)
                    *(float2*)&g_xatt[((size_t)(b*NN + r0g))*DIM + h*HD + col] =
                        make_float2(oacc[j][0], oacc[j][1]);
                if (r1g < NN)
                    *(float2*)&g_xatt[((size_t)(b*NN + r1g))*DIM + h*HD + col] =
                        make_float2(oacc[j][2], oacc[j][3]);
            }
        }
        __syncthreads();
    }
}

// ---------------- cls reduce ----------------
__global__ void cls_reduce_kernel() {
    int i = blockIdx.x*256 + threadIdx.x;
    if (i < BB*384) {
        int b = i / 384, j = i % 384;
        float s = 0.f;
#pragma unroll
        for (int h = 0; h < HH; h++) s += g_clsP[((size_t)b*HH + h)*384 + j];
        g_cls[i] = s;
    }
}

// ---------------- top-k (exact jax tie semantics) ----------------
__global__ void topk_kernel(float* __restrict__ out) {
    const int nsz_[3]  = {64, 192, 128};
    const int kk_[3]   = {KA, KM, KS};
    const int base_[3] = {0, 64, 256};
    const int ib_[3]   = {0, KA, KA+KM};
    const long long ob_[3] = {OFF_IA, OFF_IM, OFF_IS};
    const int os_[3]   = {KA, KM, KS};

    int b = blockIdx.x / 3, g = blockIdx.x % 3;
    int nsz = nsz_[g], kk = kk_[g];
    __shared__ float v[192];
    __shared__ float rv[256];
    __shared__ int   ri[256];
    int t = threadIdx.x;
    if (t < nsz) v[t] = g_cls[b*384 + base_[g] + t];
    __syncthreads();

    for (int i = 0; i < kk; i++) {
        rv[t] = (t < nsz) ? v[t] : -INFINITY;
        ri[t] = t;
        __syncthreads();
        for (int s = 128; s > 0; s >>= 1) {
            if (t < s) {
                float v2 = rv[t+s]; int i2 = ri[t+s];
                if (v2 > rv[t] || (v2 == rv[t] && i2 < ri[t])) { rv[t] = v2; ri[t] = i2; }
            }
            __syncthreads();
        }
        if (t == 0) {
            int wn = ri[0];
            g_idx[b*(KA+KM+KS) + ib_[g] + i] = wn;
            out[ob_[g] + (long long)b*os_[g] + i] = (float)wn;
            v[wn] = -INFINITY;
        }
        __syncthreads();
    }
}

// ---------------- gather ----------------
__global__ void gather_kernel() {
    int r = blockIdx.x;
    int b = r / RN, p = r % RN;
    int s;
    if (p == 0)            s = 0;
    else if (p < 1+KA)     s = 1   + g_idx[b*(KA+KM+KS) + (p-1)];
    else if (p < 1+KA+KM)  s = 65  + g_idx[b*(KA+KM+KS) + KA + (p-1-KA)];
    else                   s = 257 + g_idx[b*(KA+KM+KS) + KA+KM + (p-1-KA-KM)];
    const float4* src = reinterpret_cast<const float4*>(g_xres + ((size_t)(b*NN + s))*DIM);
    float4* dst = reinterpret_cast<float4*>(g_xg + (size_t)r*DIM);
    dst[threadIdx.x] = src[threadIdx.x];
}

// ---------------- mask = ones (vectorized) ----------------
__global__ void mask_fill_kernel(float* __restrict__ out) {
    long long i = (long long)blockIdx.x*256 + threadIdx.x;
    if (i < MASK_SZ/4) {
        float4* o = reinterpret_cast<float4*>(out + OFF_MASK);
        o[i] = make_float4(1.f,1.f,1.f,1.f);
    }
}

// ---------------- launcher ----------------
extern "C" void kernel_launch(void* const* d_in, const int* in_sizes, int n_in,
                              void* d_out, int out_size) {
    const float* x     = (const float*)d_in[0];
    const float* amask = (const float*)d_in[1];
    const float* Wqkv  = (const float*)d_in[5];
    const float* Wproj = (const float*)d_in[6];
    const float* bproj = (const float*)d_in[7];
    const float* g1    = (const float*)d_in[8];
    const float* b1    = (const float*)d_in[9];
    const float* g2    = (const float*)d_in[10];
    const float* b2    = (const float*)d_in[11];
    const float* Wfc1  = (const float*)d_in[12];
    const float* bfc1  = (const float*)d_in[13];
    const float* Wfc2  = (const float*)d_in[14];
    const float* bfc2  = (const float*)d_in[15];
    float* out = (float*)d_out;

    float *p_xn, *p_qkv, *p_xatt, *p_xres, *p_xg, *p_xn2, *p_h;
    cudaGetSymbolAddress((void**)&p_xn,   g_xn);
    cudaGetSymbolAddress((void**)&p_qkv,  g_qkv);
    cudaGetSymbolAddress((void**)&p_xatt, g_xatt);
    cudaGetSymbolAddress((void**)&p_xres, g_xres);
    cudaGetSymbolAddress((void**)&p_xg,   g_xg);
    cudaGetSymbolAddress((void**)&p_xn2,  g_xn2);
    cudaGetSymbolAddress((void**)&p_h,    g_h);

    const int SMEM_S = 4*GTS*4;                 // 40960 B
    const int ATTN_SMEM = ATTN_WORDS * 4;       // 170,048 B
    static int init_done = 0;
    if (!init_done) {
        cudaFuncSetAttribute(gemm_mma<0>, cudaFuncAttributeMaxDynamicSharedMemorySize, SMEM_S);
        cudaFuncSetAttribute(gemm_mma<1>, cudaFuncAttributeMaxDynamicSharedMemorySize, SMEM_S);
        cudaFuncSetAttribute(gemm_mma<2>, cudaFuncAttributeMaxDynamicSharedMemorySize, SMEM_S);
        cudaFuncSetAttribute(attn_kernel, cudaFuncAttributeMaxDynamicSharedMemorySize, ATTN_SMEM);
        init_done = 1;
    }

    ln_kernel<<<M1, 256>>>(x, g1, b1, p_xn);
    gemm_mma<0><<<dim3(4, (M1+127)/128), 256, SMEM_S>>>(p_xn, Wqkv,            nullptr, nullptr, p_qkv,        M1, 512, DIM, TDIM);
    gemm_mma<0><<<dim3(4, (M1+127)/128), 256, SMEM_S>>>(p_xn, Wqkv + 1024*512, nullptr, nullptr, p_qkv + 1024, M1, 512, DIM, TDIM);
    gemm_f32<<<dim3(4, (M1+127)/128), 256>>>(p_xn, Wqkv + 512*512, p_qkv + 512, M1, 512, DIM, TDIM);
    q0_exact<<<BB, 512>>>(Wqkv);
    attn_kernel<<<BB*HH, 256, ATTN_SMEM>>>(amask);
    gemm_mma<1><<<dim3(DIM/128, (M1+127)/128), 256, SMEM_S>>>(p_xatt, Wproj, bproj, x, p_xres, M1, DIM, DIM, DIM);
    cls_reduce_kernel<<<(BB*384 + 255)/256, 256>>>();
    topk_kernel<<<BB*3, 256>>>(out);
    gather_kernel<<<M2, 128>>>();
    mask_fill_kernel<<<(int)((MASK_SZ/4 + 255)/256), 256>>>(out);
    ln_kernel<<<M2, 256>>>(p_xg, g2, b2, p_xn2);
    gemm_mma<2><<<dim3(MLP/128, (M2+127)/128), 256, SMEM_S>>>(p_xn2, Wfc1, bfc1, nullptr, p_h, M2, MLP, DIM, MLP);
    gemm_mma<1><<<dim3(DIM/128, (M2+127)/128), 256, SMEM_S>>>(p_h, Wfc2, bfc2, p_xg, out, M2, DIM, MLP, DIM);
}